// round 2
// baseline (speedup 1.0000x reference)
#include <cuda_runtime.h>
#include <cuda_bf16.h>
#include <cstdint>

#define NNODES 100000
#define NEDGES 1600000
#define F_IN   256
#define HID    128
#define NL     4
#define NCOLS  40
#define JKDIM  (HID * NL)   // 512

// ---------------- device scratch (allocation-free rule: __device__ globals) --------
__device__ float g_t[(size_t)NNODES * HID];          // GEMM output / agg input (51.2 MB)
__device__ float g_h[(size_t)NNODES * JKDIM];        // JK concat buffer (204.8 MB)
__device__ int   g_cnt[NNODES];                      // in-degree counts (excl. self loop)
__device__ int   g_cur[NNODES];                      // placement cursors
__device__ int   g_off[NNODES + 1];                  // CSR row offsets
__device__ float g_dis[NNODES];                      // deg^{-1/2}
__device__ int   g_col[NEDGES];                      // CSR column (src) indices
__device__ float g_norm[NEDGES];                     // per-edge dis[src]*dis[dst]
__device__ int   g_bsum[128];                        // scan block sums

#define SCAN_B 1024
#define NB_SCAN ((NNODES + SCAN_B - 1) / SCAN_B)     // 98

// ---------------- CSR construction ------------------------------------------------
__global__ void k_zero() {
    int i = blockIdx.x * blockDim.x + threadIdx.x;
    if (i < NNODES) { g_cnt[i] = 0; g_cur[i] = 0; }
}

__global__ void k_count(const int* __restrict__ dst) {
    int e = blockIdx.x * blockDim.x + threadIdx.x;
    if (e < NEDGES) atomicAdd(&g_cnt[dst[e]], 1);
}

__global__ void k_dis() {
    int i = blockIdx.x * blockDim.x + threadIdx.x;
    if (i < NNODES) g_dis[i] = rsqrtf((float)(g_cnt[i] + 1));  // +1 self loop
}

__global__ void k_scan1() {
    __shared__ int s[SCAN_B];
    int tid = threadIdx.x;
    int idx = blockIdx.x * SCAN_B + tid;
    int v = (idx < NNODES) ? g_cnt[idx] : 0;
    s[tid] = v;
    __syncthreads();
    #pragma unroll
    for (int o = 1; o < SCAN_B; o <<= 1) {
        int t = (tid >= o) ? s[tid - o] : 0;
        __syncthreads();
        s[tid] += t;
        __syncthreads();
    }
    if (idx < NNODES) g_off[idx] = s[tid] - v;   // local exclusive
    if (tid == SCAN_B - 1) g_bsum[blockIdx.x] = s[tid];
}

__global__ void k_scan2() {
    __shared__ int s[128];
    int tid = threadIdx.x;
    if (tid < NB_SCAN) s[tid] = g_bsum[tid];
    __syncthreads();
    if (tid == 0) {
        int a = 0;
        for (int i = 0; i < NB_SCAN; i++) { int t = s[i]; s[i] = a; a += t; }
    }
    __syncthreads();
    if (tid < NB_SCAN) g_bsum[tid] = s[tid];
}

__global__ void k_scan3() {
    int idx = blockIdx.x * SCAN_B + threadIdx.x;
    if (idx < NNODES) g_off[idx] += g_bsum[blockIdx.x];
    if (idx == 0) g_off[NNODES] = NEDGES;
}

__global__ void k_fill(const int* __restrict__ src, const int* __restrict__ dst) {
    int e = blockIdx.x * blockDim.x + threadIdx.x;
    if (e < NEDGES) {
        int d = dst[e];
        int s = src[e];
        int pos = g_off[d] + atomicAdd(&g_cur[d], 1);
        g_col[pos] = s;
        g_norm[pos] = g_dis[s] * g_dis[d];
    }
}

// ---------------- GEMM (layer 0): x[N x 256] @ W[256 x 128] -> g_t -----------------
// and GEMM (layers 1-3): g_h[:, off:off+128] @ W -> g_t.
// Block tile 64 rows x 128 cols, 256 threads, thread tile 4x8.
// A source selected by template flag: FROM_H=0 -> runtime pointer A (lda=K),
// FROM_H=1 -> g_h with lda=JKDIM and column offset src_off.
template <int K, int FROM_H>
__global__ void k_gemm_n128(const float* __restrict__ A, int src_off,
                            const float* __restrict__ W) {
    constexpr int BM = 64, BK = 16;
    __shared__ float As[BM][BK];
    __shared__ float Ws[BK][HID];

    int tid = threadIdx.x;
    int cg = tid & 15;    // col group -> cols cg*8 .. cg*8+7
    int rg = tid >> 4;    // row group -> rows rg*4 .. rg*4+3
    int row0 = blockIdx.x * BM;

    float4 acc0[4], acc1[4];
    #pragma unroll
    for (int i = 0; i < 4; i++) {
        acc0[i] = make_float4(0.f, 0.f, 0.f, 0.f);
        acc1[i] = make_float4(0.f, 0.f, 0.f, 0.f);
    }

    for (int kc = 0; kc < K; kc += BK) {
        // stage A tile (64x16): 256 float4 loads, one per thread
        {
            int r  = tid >> 2;
            int c4 = tid & 3;
            float4 v = make_float4(0.f, 0.f, 0.f, 0.f);
            int gr = row0 + r;
            if (gr < NNODES) {
                if (FROM_H)
                    v = *(const float4*)(g_h + (size_t)gr * JKDIM + src_off + kc + c4 * 4);
                else
                    v = *(const float4*)(A + (size_t)gr * K + kc + c4 * 4);
            }
            *(float4*)&As[r][c4 * 4] = v;
        }
        // stage W tile (16x128): 512 float4, two per thread
        #pragma unroll
        for (int i = 0; i < 2; i++) {
            int idx = tid + i * 256;
            int wr = idx >> 5;
            int wc = idx & 31;
            *(float4*)&Ws[wr][wc * 4] =
                *(const float4*)(W + (size_t)(kc + wr) * HID + wc * 4);
        }
        __syncthreads();

        #pragma unroll
        for (int kk = 0; kk < BK; kk++) {
            float4 w0 = *(float4*)&Ws[kk][cg * 8];
            float4 w1 = *(float4*)&Ws[kk][cg * 8 + 4];
            #pragma unroll
            for (int i = 0; i < 4; i++) {
                float a = As[rg * 4 + i][kk];
                acc0[i].x += a * w0.x; acc0[i].y += a * w0.y;
                acc0[i].z += a * w0.z; acc0[i].w += a * w0.w;
                acc1[i].x += a * w1.x; acc1[i].y += a * w1.y;
                acc1[i].z += a * w1.z; acc1[i].w += a * w1.w;
            }
        }
        __syncthreads();
    }

    #pragma unroll
    for (int i = 0; i < 4; i++) {
        int row = row0 + rg * 4 + i;
        if (row < NNODES) {
            *(float4*)(g_t + (size_t)row * HID + cg * 8)     = acc0[i];
            *(float4*)(g_t + (size_t)row * HID + cg * 8 + 4) = acc1[i];
        }
    }
}

// ---------------- Aggregation: h[:, dst_off:+128] = relu(D^-1/2 A D^-1/2 t + b) ----
// One warp per node; lane handles 4 consecutive features (float4).
__global__ void k_agg(const float* __restrict__ bias, int dst_off) {
    int node = blockIdx.x * 8 + (threadIdx.x >> 5);
    if (node >= NNODES) return;
    int lane = threadIdx.x & 31;

    const float4* t4 = (const float4*)g_t;
    float d = __ldg(&g_dis[node]);
    float sl = d * d;
    float4 self = __ldg(&t4[(size_t)node * 32 + lane]);
    float4 acc = make_float4(sl * self.x, sl * self.y, sl * self.z, sl * self.w);

    int e   = g_off[node];
    int end = g_off[node + 1];

    // unroll by 2 for MLP on the gathered rows
    for (; e + 1 < end; e += 2) {
        int   s0 = __ldg(&g_col[e]);
        int   s1 = __ldg(&g_col[e + 1]);
        float n0 = __ldg(&g_norm[e]);
        float n1 = __ldg(&g_norm[e + 1]);
        float4 v0 = __ldg(&t4[(size_t)s0 * 32 + lane]);
        float4 v1 = __ldg(&t4[(size_t)s1 * 32 + lane]);
        acc.x += n0 * v0.x + n1 * v1.x;
        acc.y += n0 * v0.y + n1 * v1.y;
        acc.z += n0 * v0.z + n1 * v1.z;
        acc.w += n0 * v0.w + n1 * v1.w;
    }
    if (e < end) {
        int   s0 = __ldg(&g_col[e]);
        float n0 = __ldg(&g_norm[e]);
        float4 v0 = __ldg(&t4[(size_t)s0 * 32 + lane]);
        acc.x += n0 * v0.x; acc.y += n0 * v0.y;
        acc.z += n0 * v0.z; acc.w += n0 * v0.w;
    }

    float4 bb = __ldg((const float4*)(bias) + lane);
    acc.x = fmaxf(acc.x + bb.x, 0.f);
    acc.y = fmaxf(acc.y + bb.y, 0.f);
    acc.z = fmaxf(acc.z + bb.z, 0.f);
    acc.w = fmaxf(acc.w + bb.w, 0.f);

    *(float4*)(g_h + (size_t)node * JKDIM + dst_off + lane * 4) = acc;
}

// ---------------- Output GEMM: g_h[N x 512] @ [512 x 40] + b -> out ----------------
// Block tile 128 rows x 40 cols, 320 threads, thread tile 4x4.
__global__ void k_gemm_out(const float* __restrict__ W,
                           const float* __restrict__ b,
                           float* __restrict__ C) {
    constexpr int BM = 128, BK = 16, K = JKDIM;
    __shared__ float As[BM][BK];
    __shared__ float Ws[BK][NCOLS];

    int tid = threadIdx.x;           // 320
    int cg = tid % 10;               // cols cg*4
    int rg = tid / 10;               // rows rg*4 (0..31)
    int row0 = blockIdx.x * BM;

    float4 acc[4];
    #pragma unroll
    for (int i = 0; i < 4; i++) acc[i] = make_float4(0.f, 0.f, 0.f, 0.f);

    for (int kc = 0; kc < K; kc += BK) {
        // A tile: 128x16 = 512 float4
        for (int idx = tid; idx < 512; idx += 320) {
            int r  = idx >> 2;
            int c4 = idx & 3;
            float4 v = make_float4(0.f, 0.f, 0.f, 0.f);
            int gr = row0 + r;
            if (gr < NNODES)
                v = *(const float4*)(g_h + (size_t)gr * K + kc + c4 * 4);
            *(float4*)&As[r][c4 * 4] = v;
        }
        // W tile: 16x40 = 160 float4
        if (tid < 160) {
            int wr = tid / 10;
            int wc = tid % 10;
            *(float4*)&Ws[wr][wc * 4] =
                *(const float4*)(W + (size_t)(kc + wr) * NCOLS + wc * 4);
        }
        __syncthreads();

        #pragma unroll
        for (int kk = 0; kk < BK; kk++) {
            float4 w = *(float4*)&Ws[kk][cg * 4];
            #pragma unroll
            for (int i = 0; i < 4; i++) {
                float a = As[rg * 4 + i][kk];
                acc[i].x += a * w.x; acc[i].y += a * w.y;
                acc[i].z += a * w.z; acc[i].w += a * w.w;
            }
        }
        __syncthreads();
    }

    float4 bb = *(const float4*)(b + cg * 4);
    #pragma unroll
    for (int i = 0; i < 4; i++) {
        int row = row0 + rg * 4 + i;
        if (row < NNODES) {
            float4 o = make_float4(acc[i].x + bb.x, acc[i].y + bb.y,
                                   acc[i].z + bb.z, acc[i].w + bb.w);
            *(float4*)(C + (size_t)row * NCOLS + cg * 4) = o;
        }
    }
}

// ---------------- launch ----------------------------------------------------------
extern "C" void kernel_launch(void* const* d_in, const int* in_sizes, int n_in,
                              void* d_out, int out_size) {
    const float* x     = (const float*)d_in[0];
    const int*   ei    = (const int*)d_in[1];
    const float* W_in  = (const float*)d_in[2];
    const float* b_in  = (const float*)d_in[3];
    const float* W1    = (const float*)d_in[4];
    const float* b1    = (const float*)d_in[5];
    const float* W2    = (const float*)d_in[6];
    const float* b2    = (const float*)d_in[7];
    const float* W3    = (const float*)d_in[8];
    const float* b3    = (const float*)d_in[9];
    const float* W_out = (const float*)d_in[10];
    const float* b_out = (const float*)d_in[11];
    float* out = (float*)d_out;

    const int* src = ei;            // edge_index[0]
    const int* dst = ei + NEDGES;   // edge_index[1]

    // --- CSR build ---
    k_zero<<<(NNODES + 255) / 256, 256>>>();
    k_count<<<(NEDGES + 255) / 256, 256>>>(dst);
    k_dis<<<(NNODES + 255) / 256, 256>>>();
    k_scan1<<<NB_SCAN, SCAN_B>>>();
    k_scan2<<<1, 128>>>();
    k_scan3<<<NB_SCAN, SCAN_B>>>();
    k_fill<<<(NEDGES + 255) / 256, 256>>>(src, dst);

    const int gemm_grid = (NNODES + 63) / 64;
    const int agg_grid  = (NNODES + 7) / 8;

    // --- layer 0: t = x @ W_in ; h[:,0:128] = relu(Agg(t) + b_in) ---
    k_gemm_n128<F_IN, 0><<<gemm_grid, 256>>>(x, 0, W_in);
    k_agg<<<agg_grid, 256>>>(b_in, 0 * HID);

    // --- layers 1..3: t = h[:, (l-1)*128 : l*128] @ W ; h[:, l*128:...] = ... ---
    const float* Ws[3] = {W1, W2, W3};
    const float* bs[3] = {b1, b2, b3};
    for (int l = 1; l < NL; l++) {
        k_gemm_n128<HID, 1><<<gemm_grid, 256>>>(nullptr, (l - 1) * HID, Ws[l - 1]);
        k_agg<<<agg_grid, 256>>>(bs[l - 1], l * HID);
    }

    // --- JK output: out = hcat @ W_out + b_out ---
    k_gemm_out<<<(NNODES + 127) / 128, 320>>>(W_out, b_out, out);
}

// round 4
// speedup vs baseline: 2.0239x; 2.0239x over previous
#include <cuda_runtime.h>
#include <cuda_bf16.h>
#include <cstdint>

#define NNODES 100000
#define NEDGES 1600000
#define F_IN   256
#define HID    128
#define NL     4
#define NCOLS  40
#define JKDIM  (HID * NL)   // 512

// ---------------- device scratch (allocation-free rule: __device__ globals) --------
__device__ float g_t[(size_t)NNODES * HID];          // u = dis * (A@W)  (51.2 MB)
__device__ float g_h[(size_t)NNODES * JKDIM];        // JK concat buffer (204.8 MB)
__device__ int   g_cnt[NNODES];                      // in-degree counts (excl. self loop)
__device__ int   g_cur[NNODES];                      // placement cursors
__device__ int   g_off[NNODES + 1];                  // CSR row offsets
__device__ float g_dis[NNODES];                      // deg^{-1/2}
__device__ int   g_col[NEDGES];                      // CSR column (src) indices
__device__ int   g_bsum[128];                        // scan block sums

#define SCAN_B 1024
#define NB_SCAN ((NNODES + SCAN_B - 1) / SCAN_B)     // 98

// ---------------- tf32 helpers -----------------------------------------------------
__device__ __forceinline__ uint32_t f2tf32(float f) {
    uint32_t r;
    asm("cvt.rna.tf32.f32 %0, %1;" : "=r"(r) : "f"(f));
    return r;
}

__device__ __forceinline__ void mma_tf32(float4& c, const uint32_t a[4],
                                         uint32_t b0, uint32_t b1) {
    asm volatile(
        "mma.sync.aligned.m16n8k8.row.col.f32.tf32.tf32.f32 "
        "{%0,%1,%2,%3}, {%4,%5,%6,%7}, {%8,%9}, {%0,%1,%2,%3};"
        : "+f"(c.x), "+f"(c.y), "+f"(c.z), "+f"(c.w)
        : "r"(a[0]), "r"(a[1]), "r"(a[2]), "r"(a[3]), "r"(b0), "r"(b1));
}

// ---------------- CSR construction ------------------------------------------------
__global__ void k_zero() {
    int i = blockIdx.x * blockDim.x + threadIdx.x;
    if (i < NNODES) { g_cnt[i] = 0; g_cur[i] = 0; }
}

__global__ void k_count(const int* __restrict__ dst) {
    int e = blockIdx.x * blockDim.x + threadIdx.x;
    if (e < NEDGES) atomicAdd(&g_cnt[dst[e]], 1);
}

__global__ void k_dis() {
    int i = blockIdx.x * blockDim.x + threadIdx.x;
    if (i < NNODES) g_dis[i] = rsqrtf((float)(g_cnt[i] + 1));  // +1 self loop
}

__global__ void k_scan1() {
    __shared__ int s[SCAN_B];
    int tid = threadIdx.x;
    int idx = blockIdx.x * SCAN_B + tid;
    int v = (idx < NNODES) ? g_cnt[idx] : 0;
    s[tid] = v;
    __syncthreads();
    #pragma unroll
    for (int o = 1; o < SCAN_B; o <<= 1) {
        int t = (tid >= o) ? s[tid - o] : 0;
        __syncthreads();
        s[tid] += t;
        __syncthreads();
    }
    if (idx < NNODES) g_off[idx] = s[tid] - v;   // local exclusive
    if (tid == SCAN_B - 1) g_bsum[blockIdx.x] = s[tid];
}

__global__ void k_scan2() {
    __shared__ int s[128];
    int tid = threadIdx.x;
    if (tid < NB_SCAN) s[tid] = g_bsum[tid];
    __syncthreads();
    if (tid == 0) {
        int a = 0;
        for (int i = 0; i < NB_SCAN; i++) { int t = s[i]; s[i] = a; a += t; }
    }
    __syncthreads();
    if (tid < NB_SCAN) g_bsum[tid] = s[tid];
}

__global__ void k_scan3() {
    int idx = blockIdx.x * SCAN_B + threadIdx.x;
    if (idx < NNODES) g_off[idx] += g_bsum[blockIdx.x];
    if (idx == 0) g_off[NNODES] = NEDGES;
}

__global__ void k_fill(const int* __restrict__ src, const int* __restrict__ dst) {
    int e = blockIdx.x * blockDim.x + threadIdx.x;
    if (e < NEDGES) {
        int d = dst[e];
        int pos = g_off[d] + atomicAdd(&g_cur[d], 1);
        g_col[pos] = src[e];
    }
}

// ---------------- tf32 GEMM: [N x K] @ [K x 128] -> g_t (scaled by dis[row]) -------
// BM=128, BN=128(all), BK=32; 8 warps (4 m-groups x 2 n-groups); warp tile 32x64.
// FROM_H=1 reads g_h with row stride JKDIM at column src_off.
template <int K, int FROM_H>
__global__ void __launch_bounds__(256) k_gemm_tf32(const float* __restrict__ A,
                                                   int src_off,
                                                   const float* __restrict__ W) {
    constexpr int BM = 128, BK = 32;
    __shared__ uint32_t As[BM][36];     // pad: bank = (4r + c) % 32
    __shared__ uint32_t Ws[BK][132];    // pad: bank = (4k + n) % 32

    int tid = threadIdx.x;
    int lane = tid & 31, wid = tid >> 5;
    int warp_m = wid & 3, warp_n = wid >> 2;
    int row0 = blockIdx.x * BM;
    int g = lane >> 2, tg = lane & 3;

    const int lda = FROM_H ? JKDIM : K;
    const float* Abase = FROM_H ? (g_h + src_off) : A;

    float4 c[2][8];
    #pragma unroll
    for (int mt = 0; mt < 2; mt++)
        #pragma unroll
        for (int nt = 0; nt < 8; nt++)
            c[mt][nt] = make_float4(0.f, 0.f, 0.f, 0.f);

    for (int kc = 0; kc < K; kc += BK) {
        // stage A (128x32): 1024 float4, 4 per thread
        #pragma unroll
        for (int j = 0; j < 4; j++) {
            int idx = tid + j * 256;
            int r = idx >> 3, c4 = idx & 7;
            int gr = row0 + r;
            float4 v = make_float4(0.f, 0.f, 0.f, 0.f);
            if (gr < NNODES)
                v = *(const float4*)(Abase + (size_t)gr * lda + kc + c4 * 4);
            uint4 u = make_uint4(f2tf32(v.x), f2tf32(v.y), f2tf32(v.z), f2tf32(v.w));
            *(uint4*)&As[r][c4 * 4] = u;
        }
        // stage W (32x128): 1024 float4, 4 per thread
        #pragma unroll
        for (int j = 0; j < 4; j++) {
            int idx = tid + j * 256;
            int wr = idx >> 5, wc = idx & 31;
            float4 v = *(const float4*)(W + (size_t)(kc + wr) * HID + wc * 4);
            uint4 u = make_uint4(f2tf32(v.x), f2tf32(v.y), f2tf32(v.z), f2tf32(v.w));
            *(uint4*)&Ws[wr][wc * 4] = u;
        }
        __syncthreads();

        #pragma unroll
        for (int ks = 0; ks < BK; ks += 8) {
            uint32_t a[2][4];
            #pragma unroll
            for (int mt = 0; mt < 2; mt++) {
                int r = warp_m * 32 + mt * 16 + g;
                a[mt][0] = As[r][ks + tg];
                a[mt][1] = As[r + 8][ks + tg];
                a[mt][2] = As[r][ks + tg + 4];
                a[mt][3] = As[r + 8][ks + tg + 4];
            }
            #pragma unroll
            for (int nt = 0; nt < 8; nt++) {
                int n = warp_n * 64 + nt * 8 + g;
                uint32_t b0 = Ws[ks + tg][n];
                uint32_t b1 = Ws[ks + tg + 4][n];
                #pragma unroll
                for (int mt = 0; mt < 2; mt++)
                    mma_tf32(c[mt][nt], a[mt], b0, b1);
            }
        }
        __syncthreads();
    }

    // epilogue: u = dis[row] * acc -> g_t
    #pragma unroll
    for (int mt = 0; mt < 2; mt++) {
        int r_lo = row0 + warp_m * 32 + mt * 16 + g;
        int r_hi = r_lo + 8;
        float dlo = (r_lo < NNODES) ? g_dis[r_lo] : 0.f;
        float dhi = (r_hi < NNODES) ? g_dis[r_hi] : 0.f;
        #pragma unroll
        for (int nt = 0; nt < 8; nt++) {
            int col = warp_n * 64 + nt * 8 + 2 * tg;
            if (r_lo < NNODES) {
                float2 v = make_float2(c[mt][nt].x * dlo, c[mt][nt].y * dlo);
                *(float2*)(g_t + (size_t)r_lo * HID + col) = v;
            }
            if (r_hi < NNODES) {
                float2 v = make_float2(c[mt][nt].z * dhi, c[mt][nt].w * dhi);
                *(float2*)(g_t + (size_t)r_hi * HID + col) = v;
            }
        }
    }
}

// ---------------- Aggregation: h[:, dst_off:+128] = relu(dis[d]*(u[d]+Σu[s]) + b) --
// One warp per node; lane handles 4 consecutive features (float4).
__global__ void k_agg(const float* __restrict__ bias, int dst_off) {
    int node = blockIdx.x * 8 + (threadIdx.x >> 5);
    if (node >= NNODES) return;
    int lane = threadIdx.x & 31;

    const float4* t4 = (const float4*)g_t;
    float4 acc = __ldg(&t4[(size_t)node * 32 + lane]);   // u[node] (self loop)

    int e   = g_off[node];
    int end = g_off[node + 1];

    for (; e + 3 < end; e += 4) {
        int s0 = __ldg(&g_col[e]);
        int s1 = __ldg(&g_col[e + 1]);
        int s2 = __ldg(&g_col[e + 2]);
        int s3 = __ldg(&g_col[e + 3]);
        float4 v0 = __ldg(&t4[(size_t)s0 * 32 + lane]);
        float4 v1 = __ldg(&t4[(size_t)s1 * 32 + lane]);
        float4 v2 = __ldg(&t4[(size_t)s2 * 32 + lane]);
        float4 v3 = __ldg(&t4[(size_t)s3 * 32 + lane]);
        acc.x += (v0.x + v1.x) + (v2.x + v3.x);
        acc.y += (v0.y + v1.y) + (v2.y + v3.y);
        acc.z += (v0.z + v1.z) + (v2.z + v3.z);
        acc.w += (v0.w + v1.w) + (v2.w + v3.w);
    }
    for (; e < end; e++) {
        int s0 = __ldg(&g_col[e]);
        float4 v0 = __ldg(&t4[(size_t)s0 * 32 + lane]);
        acc.x += v0.x; acc.y += v0.y; acc.z += v0.z; acc.w += v0.w;
    }

    float dnode = __ldg(&g_dis[node]);
    float4 bb = __ldg((const float4*)(bias) + lane);
    acc.x = fmaxf(fmaf(dnode, acc.x, bb.x), 0.f);
    acc.y = fmaxf(fmaf(dnode, acc.y, bb.y), 0.f);
    acc.z = fmaxf(fmaf(dnode, acc.z, bb.z), 0.f);
    acc.w = fmaxf(fmaf(dnode, acc.w, bb.w), 0.f);

    *(float4*)(g_h + (size_t)node * JKDIM + dst_off + lane * 4) = acc;
}

// ---------------- tf32 output GEMM: g_h[N x 512] @ [512 x 40] + b -> out -----------
// BM=128, BK=32; 8 warps, each one m16 band covering all 40 cols (5 n8 tiles).
__global__ void __launch_bounds__(256) k_gemm_out_tf32(const float* __restrict__ W,
                                                       const float* __restrict__ b,
                                                       float* __restrict__ C) {
    constexpr int BM = 128, BK = 32, K = JKDIM;
    __shared__ uint32_t As[BM][36];
    __shared__ uint32_t Ws[BK][44];     // pad: bank = (12k + n) % 32

    int tid = threadIdx.x;
    int lane = tid & 31, wid = tid >> 5;
    int row0 = blockIdx.x * BM;
    int g = lane >> 2, tg = lane & 3;
    int m0 = wid * 16;

    float4 c[5];
    #pragma unroll
    for (int nt = 0; nt < 5; nt++) c[nt] = make_float4(0.f, 0.f, 0.f, 0.f);

    for (int kc = 0; kc < K; kc += BK) {
        // stage A (128x32)
        #pragma unroll
        for (int j = 0; j < 4; j++) {
            int idx = tid + j * 256;
            int r = idx >> 3, c4 = idx & 7;
            int gr = row0 + r;
            float4 v = make_float4(0.f, 0.f, 0.f, 0.f);
            if (gr < NNODES)
                v = *(const float4*)(g_h + (size_t)gr * K + kc + c4 * 4);
            uint4 u = make_uint4(f2tf32(v.x), f2tf32(v.y), f2tf32(v.z), f2tf32(v.w));
            *(uint4*)&As[r][c4 * 4] = u;
        }
        // stage W (32x40): 320 float4
        for (int idx = tid; idx < 320; idx += 256) {
            int wr = idx / 10, wc = idx % 10;
            float4 v = *(const float4*)(W + (size_t)(kc + wr) * NCOLS + wc * 4);
            uint4 u = make_uint4(f2tf32(v.x), f2tf32(v.y), f2tf32(v.z), f2tf32(v.w));
            *(uint4*)&Ws[wr][wc * 4] = u;
        }
        __syncthreads();

        #pragma unroll
        for (int ks = 0; ks < BK; ks += 8) {
            uint32_t a[4];
            int r = m0 + g;
            a[0] = As[r][ks + tg];
            a[1] = As[r + 8][ks + tg];
            a[2] = As[r][ks + tg + 4];
            a[3] = As[r + 8][ks + tg + 4];
            #pragma unroll
            for (int nt = 0; nt < 5; nt++) {
                int n = nt * 8 + g;
                uint32_t b0 = Ws[ks + tg][n];
                uint32_t b1 = Ws[ks + tg + 4][n];
                mma_tf32(c[nt], a, b0, b1);
            }
        }
        __syncthreads();
    }

    int r_lo = row0 + m0 + g;
    int r_hi = r_lo + 8;
    #pragma unroll
    for (int nt = 0; nt < 5; nt++) {
        int col = nt * 8 + 2 * tg;
        float b0 = __ldg(&b[col]), b1 = __ldg(&b[col + 1]);
        if (r_lo < NNODES) {
            float2 v = make_float2(c[nt].x + b0, c[nt].y + b1);
            *(float2*)(C + (size_t)r_lo * NCOLS + col) = v;
        }
        if (r_hi < NNODES) {
            float2 v = make_float2(c[nt].z + b0, c[nt].w + b1);
            *(float2*)(C + (size_t)r_hi * NCOLS + col) = v;
        }
    }
}

// ---------------- launch ----------------------------------------------------------
extern "C" void kernel_launch(void* const* d_in, const int* in_sizes, int n_in,
                              void* d_out, int out_size) {
    const float* x     = (const float*)d_in[0];
    const int*   ei    = (const int*)d_in[1];
    const float* W_in  = (const float*)d_in[2];
    const float* b_in  = (const float*)d_in[3];
    const float* W1    = (const float*)d_in[4];
    const float* b1    = (const float*)d_in[5];
    const float* W2    = (const float*)d_in[6];
    const float* b2    = (const float*)d_in[7];
    const float* W3    = (const float*)d_in[8];
    const float* b3    = (const float*)d_in[9];
    const float* W_out = (const float*)d_in[10];
    const float* b_out = (const float*)d_in[11];
    float* out = (float*)d_out;

    const int* src = ei;            // edge_index[0]
    const int* dst = ei + NEDGES;   // edge_index[1]

    const int gemm_grid = (NNODES + 127) / 128;
    const int agg_grid  = (NNODES + 7) / 8;

    // CSR build interleaved with layer-0 GEMM (GEMM only needs g_dis).
    // Launch order puts the big GEMM at index 5 so ncu (-s 5 -c 1) captures it.
    k_zero<<<(NNODES + 255) / 256, 256>>>();                    // 0
    k_count<<<(NEDGES + 255) / 256, 256>>>(dst);                // 1
    k_dis<<<(NNODES + 255) / 256, 256>>>();                     // 2
    k_scan1<<<NB_SCAN, SCAN_B>>>();                             // 3
    k_scan2<<<1, 128>>>();                                      // 4
    k_gemm_tf32<F_IN, 0><<<gemm_grid, 256>>>(x, 0, W_in);       // 5  <- ncu target
    k_scan3<<<NB_SCAN, SCAN_B>>>();                             // 6
    k_fill<<<(NEDGES + 255) / 256, 256>>>(src, dst);            // 7
    k_agg<<<agg_grid, 256>>>(b_in, 0 * HID);                    // 8

    const float* Ws[3] = {W1, W2, W3};
    const float* bs[3] = {b1, b2, b3};
    for (int l = 1; l < NL; l++) {
        k_gemm_tf32<HID, 1><<<gemm_grid, 256>>>(nullptr, (l - 1) * HID, Ws[l - 1]);
        k_agg<<<agg_grid, 256>>>(bs[l - 1], l * HID);
    }

    k_gemm_out_tf32<<<gemm_grid, 256>>>(W_out, b_out, out);
}

// round 5
// speedup vs baseline: 2.2955x; 1.1342x over previous
#include <cuda_runtime.h>
#include <cuda_fp16.h>
#include <cstdint>

#define NNODES 100000
#define NEDGES 1600000
#define F_IN   256
#define HID    128
#define NL     4
#define NCOLS  40
#define JKDIM  (HID * NL)   // 512

// ---------------- device scratch (allocation-free rule: __device__ globals) --------
__device__ __align__(16) __half g_t[(size_t)NNODES * HID];  // u = dis*(A@W), fp16 (25.6 MB)
__device__ float g_h[(size_t)NNODES * JKDIM];        // JK concat buffer (204.8 MB)
__device__ int   g_cnt[NNODES];                      // in-degree counts (excl. self loop)
__device__ int   g_cur[NNODES];                      // placement cursors
__device__ int   g_off[NNODES + 1];                  // CSR row offsets
__device__ float g_dis[NNODES];                      // deg^{-1/2}
__device__ int   g_col[NEDGES];                      // CSR column (src) indices
__device__ int   g_bsum[128];                        // scan block sums

#define SCAN_B 1024
#define NB_SCAN ((NNODES + SCAN_B - 1) / SCAN_B)     // 98

// ---------------- tf32 helpers -----------------------------------------------------
__device__ __forceinline__ uint32_t f2tf32(float f) {
    uint32_t r;
    asm("cvt.rna.tf32.f32 %0, %1;" : "=r"(r) : "f"(f));
    return r;
}

__device__ __forceinline__ void mma_tf32(float4& c, const uint32_t a[4],
                                         uint32_t b0, uint32_t b1) {
    asm volatile(
        "mma.sync.aligned.m16n8k8.row.col.f32.tf32.tf32.f32 "
        "{%0,%1,%2,%3}, {%4,%5,%6,%7}, {%8,%9}, {%0,%1,%2,%3};"
        : "+f"(c.x), "+f"(c.y), "+f"(c.z), "+f"(c.w)
        : "r"(a[0]), "r"(a[1]), "r"(a[2]), "r"(a[3]), "r"(b0), "r"(b1));
}

// ---------------- CSR construction ------------------------------------------------
__global__ void k_zero() {
    int i = blockIdx.x * blockDim.x + threadIdx.x;
    if (i < NNODES) { g_cnt[i] = 0; g_cur[i] = 0; }
}

__global__ void k_count(const int* __restrict__ dst) {
    int e = blockIdx.x * blockDim.x + threadIdx.x;
    if (e < NEDGES) atomicAdd(&g_cnt[dst[e]], 1);
}

// scan1 also computes g_dis (reads g_cnt anyway)
__global__ void k_scan1() {
    __shared__ int s[SCAN_B];
    int tid = threadIdx.x;
    int idx = blockIdx.x * SCAN_B + tid;
    int v = (idx < NNODES) ? g_cnt[idx] : 0;
    if (idx < NNODES) g_dis[idx] = rsqrtf((float)(v + 1));   // +1 self loop
    s[tid] = v;
    __syncthreads();
    #pragma unroll
    for (int o = 1; o < SCAN_B; o <<= 1) {
        int t = (tid >= o) ? s[tid - o] : 0;
        __syncthreads();
        s[tid] += t;
        __syncthreads();
    }
    if (idx < NNODES) g_off[idx] = s[tid] - v;   // local exclusive
    if (tid == SCAN_B - 1) g_bsum[blockIdx.x] = s[tid];
}

__global__ void k_scan2() {
    __shared__ int s[128];
    int tid = threadIdx.x;
    if (tid < NB_SCAN) s[tid] = g_bsum[tid];
    __syncthreads();
    if (tid == 0) {
        int a = 0;
        for (int i = 0; i < NB_SCAN; i++) { int t = s[i]; s[i] = a; a += t; }
    }
    __syncthreads();
    if (tid < NB_SCAN) g_bsum[tid] = s[tid];
}

__global__ void k_scan3() {
    int idx = blockIdx.x * SCAN_B + threadIdx.x;
    if (idx < NNODES) g_off[idx] += g_bsum[blockIdx.x];
    if (idx == 0) g_off[NNODES] = NEDGES;
}

__global__ void k_fill(const int* __restrict__ src, const int* __restrict__ dst) {
    int e = blockIdx.x * blockDim.x + threadIdx.x;
    if (e < NEDGES) {
        int d = dst[e];
        int pos = g_off[d] + atomicAdd(&g_cur[d], 1);
        g_col[pos] = src[e];
    }
}

// ---------------- tf32 GEMM: [N x K] @ [K x 128] -> g_t (fp16, scaled by dis) ------
// BM=128, BN=128(all), BK=32; 8 warps (4 m-groups x 2 n-groups); warp tile 32x64.
// FROM_H=1 reads g_h with row stride JKDIM at column src_off.
template <int K, int FROM_H>
__global__ void __launch_bounds__(256) k_gemm_tf32(const float* __restrict__ A,
                                                   int src_off,
                                                   const float* __restrict__ W) {
    constexpr int BM = 128, BK = 32;
    __shared__ uint32_t As[BM][36];     // pad: bank = (4r + c) % 32
    __shared__ uint32_t Ws[BK][132];    // pad: bank = (4k + n) % 32

    int tid = threadIdx.x;
    int lane = tid & 31, wid = tid >> 5;
    int warp_m = wid & 3, warp_n = wid >> 2;
    int row0 = blockIdx.x * BM;
    int g = lane >> 2, tg = lane & 3;

    const int lda = FROM_H ? JKDIM : K;
    const float* Abase = FROM_H ? (g_h + src_off) : A;

    float4 c[2][8];
    #pragma unroll
    for (int mt = 0; mt < 2; mt++)
        #pragma unroll
        for (int nt = 0; nt < 8; nt++)
            c[mt][nt] = make_float4(0.f, 0.f, 0.f, 0.f);

    for (int kc = 0; kc < K; kc += BK) {
        // stage A (128x32): 1024 float4, 4 per thread
        #pragma unroll
        for (int j = 0; j < 4; j++) {
            int idx = tid + j * 256;
            int r = idx >> 3, c4 = idx & 7;
            int gr = row0 + r;
            float4 v = make_float4(0.f, 0.f, 0.f, 0.f);
            if (gr < NNODES)
                v = *(const float4*)(Abase + (size_t)gr * lda + kc + c4 * 4);
            uint4 u = make_uint4(f2tf32(v.x), f2tf32(v.y), f2tf32(v.z), f2tf32(v.w));
            *(uint4*)&As[r][c4 * 4] = u;
        }
        // stage W (32x128): 1024 float4, 4 per thread
        #pragma unroll
        for (int j = 0; j < 4; j++) {
            int idx = tid + j * 256;
            int wr = idx >> 5, wc = idx & 31;
            float4 v = *(const float4*)(W + (size_t)(kc + wr) * HID + wc * 4);
            uint4 u = make_uint4(f2tf32(v.x), f2tf32(v.y), f2tf32(v.z), f2tf32(v.w));
            *(uint4*)&Ws[wr][wc * 4] = u;
        }
        __syncthreads();

        #pragma unroll
        for (int ks = 0; ks < BK; ks += 8) {
            uint32_t a[2][4];
            #pragma unroll
            for (int mt = 0; mt < 2; mt++) {
                int r = warp_m * 32 + mt * 16 + g;
                a[mt][0] = As[r][ks + tg];
                a[mt][1] = As[r + 8][ks + tg];
                a[mt][2] = As[r][ks + tg + 4];
                a[mt][3] = As[r + 8][ks + tg + 4];
            }
            #pragma unroll
            for (int nt = 0; nt < 8; nt++) {
                int n = warp_n * 64 + nt * 8 + g;
                uint32_t b0 = Ws[ks + tg][n];
                uint32_t b1 = Ws[ks + tg + 4][n];
                #pragma unroll
                for (int mt = 0; mt < 2; mt++)
                    mma_tf32(c[mt][nt], a[mt], b0, b1);
            }
        }
        __syncthreads();
    }

    // epilogue: u = dis[row] * acc -> g_t (fp16)
    #pragma unroll
    for (int mt = 0; mt < 2; mt++) {
        int r_lo = row0 + warp_m * 32 + mt * 16 + g;
        int r_hi = r_lo + 8;
        float dlo = (r_lo < NNODES) ? g_dis[r_lo] : 0.f;
        float dhi = (r_hi < NNODES) ? g_dis[r_hi] : 0.f;
        #pragma unroll
        for (int nt = 0; nt < 8; nt++) {
            int col = warp_n * 64 + nt * 8 + 2 * tg;
            if (r_lo < NNODES) {
                __half2 v = __floats2half2_rn(c[mt][nt].x * dlo, c[mt][nt].y * dlo);
                *(__half2*)(g_t + (size_t)r_lo * HID + col) = v;
            }
            if (r_hi < NNODES) {
                __half2 v = __floats2half2_rn(c[mt][nt].z * dhi, c[mt][nt].w * dhi);
                *(__half2*)(g_t + (size_t)r_hi * HID + col) = v;
            }
        }
    }
}

// ---------------- Aggregation: h[:, dst_off:+128] = relu(dis[d]*(u[d]+Σu[s]) + b) --
// One warp per node; lane handles 4 consecutive features (8 bytes fp16).
__global__ void k_agg(const float* __restrict__ bias, int dst_off) {
    int node = blockIdx.x * 8 + (threadIdx.x >> 5);
    if (node >= NNODES) return;
    int lane = threadIdx.x & 31;

    const uint2* t2 = (const uint2*)g_t;   // 32 x 8B slots per 128-feat row

    auto fetch = [&](int row, float4& dstacc) {
        uint2 raw = __ldg(&t2[(size_t)row * 32 + lane]);
        float2 f01 = __half22float2(*(__half2*)&raw.x);
        float2 f23 = __half22float2(*(__half2*)&raw.y);
        dstacc.x += f01.x; dstacc.y += f01.y;
        dstacc.z += f23.x; dstacc.w += f23.y;
    };

    float4 acc = make_float4(0.f, 0.f, 0.f, 0.f);
    fetch(node, acc);                       // self loop (u[node])

    int e   = g_off[node];
    int end = g_off[node + 1];

    for (; e + 3 < end; e += 4) {
        int s0 = __ldg(&g_col[e]);
        int s1 = __ldg(&g_col[e + 1]);
        int s2 = __ldg(&g_col[e + 2]);
        int s3 = __ldg(&g_col[e + 3]);
        uint2 r0 = __ldg(&t2[(size_t)s0 * 32 + lane]);
        uint2 r1 = __ldg(&t2[(size_t)s1 * 32 + lane]);
        uint2 r2 = __ldg(&t2[(size_t)s2 * 32 + lane]);
        uint2 r3 = __ldg(&t2[(size_t)s3 * 32 + lane]);
        float2 a0 = __half22float2(*(__half2*)&r0.x), b0 = __half22float2(*(__half2*)&r0.y);
        float2 a1 = __half22float2(*(__half2*)&r1.x), b1 = __half22float2(*(__half2*)&r1.y);
        float2 a2 = __half22float2(*(__half2*)&r2.x), b2 = __half22float2(*(__half2*)&r2.y);
        float2 a3 = __half22float2(*(__half2*)&r3.x), b3 = __half22float2(*(__half2*)&r3.y);
        acc.x += (a0.x + a1.x) + (a2.x + a3.x);
        acc.y += (a0.y + a1.y) + (a2.y + a3.y);
        acc.z += (b0.x + b1.x) + (b2.x + b3.x);
        acc.w += (b0.y + b1.y) + (b2.y + b3.y);
    }
    for (; e < end; e++) {
        int s0 = __ldg(&g_col[e]);
        fetch(s0, acc);
    }

    float dnode = __ldg(&g_dis[node]);
    float4 bb = __ldg((const float4*)(bias) + lane);
    acc.x = fmaxf(fmaf(dnode, acc.x, bb.x), 0.f);
    acc.y = fmaxf(fmaf(dnode, acc.y, bb.y), 0.f);
    acc.z = fmaxf(fmaf(dnode, acc.z, bb.z), 0.f);
    acc.w = fmaxf(fmaf(dnode, acc.w, bb.w), 0.f);

    *(float4*)(g_h + (size_t)node * JKDIM + dst_off + lane * 4) = acc;
}

// ---------------- tf32 output GEMM: g_h[N x 512] @ [512 x 40] + b -> out -----------
// BM=128, BK=32; 8 warps, each one m16 band covering all 40 cols (5 n8 tiles).
__global__ void __launch_bounds__(256) k_gemm_out_tf32(const float* __restrict__ W,
                                                       const float* __restrict__ b,
                                                       float* __restrict__ C) {
    constexpr int BM = 128, BK = 32, K = JKDIM;
    __shared__ uint32_t As[BM][36];
    __shared__ uint32_t Ws[BK][44];     // pad: bank = (12k + n) % 32

    int tid = threadIdx.x;
    int lane = tid & 31, wid = tid >> 5;
    int row0 = blockIdx.x * BM;
    int g = lane >> 2, tg = lane & 3;
    int m0 = wid * 16;

    float4 c[5];
    #pragma unroll
    for (int nt = 0; nt < 5; nt++) c[nt] = make_float4(0.f, 0.f, 0.f, 0.f);

    for (int kc = 0; kc < K; kc += BK) {
        // stage A (128x32)
        #pragma unroll
        for (int j = 0; j < 4; j++) {
            int idx = tid + j * 256;
            int r = idx >> 3, c4 = idx & 7;
            int gr = row0 + r;
            float4 v = make_float4(0.f, 0.f, 0.f, 0.f);
            if (gr < NNODES)
                v = *(const float4*)(g_h + (size_t)gr * K + kc + c4 * 4);
            uint4 u = make_uint4(f2tf32(v.x), f2tf32(v.y), f2tf32(v.z), f2tf32(v.w));
            *(uint4*)&As[r][c4 * 4] = u;
        }
        // stage W (32x40): 320 float4
        for (int idx = tid; idx < 320; idx += 256) {
            int wr = idx / 10, wc = idx % 10;
            float4 v = *(const float4*)(W + (size_t)(kc + wr) * NCOLS + wc * 4);
            uint4 u = make_uint4(f2tf32(v.x), f2tf32(v.y), f2tf32(v.z), f2tf32(v.w));
            *(uint4*)&Ws[wr][wc * 4] = u;
        }
        __syncthreads();

        #pragma unroll
        for (int ks = 0; ks < BK; ks += 8) {
            uint32_t a[4];
            int r = m0 + g;
            a[0] = As[r][ks + tg];
            a[1] = As[r + 8][ks + tg];
            a[2] = As[r][ks + tg + 4];
            a[3] = As[r + 8][ks + tg + 4];
            #pragma unroll
            for (int nt = 0; nt < 5; nt++) {
                int n = nt * 8 + g;
                uint32_t b0 = Ws[ks + tg][n];
                uint32_t b1 = Ws[ks + tg + 4][n];
                mma_tf32(c[nt], a, b0, b1);
            }
        }
        __syncthreads();
    }

    int r_lo = row0 + m0 + g;
    int r_hi = r_lo + 8;
    #pragma unroll
    for (int nt = 0; nt < 5; nt++) {
        int col = nt * 8 + 2 * tg;
        float b0 = __ldg(&b[col]), b1 = __ldg(&b[col + 1]);
        if (r_lo < NNODES) {
            float2 v = make_float2(c[nt].x + b0, c[nt].y + b1);
            *(float2*)(C + (size_t)r_lo * NCOLS + col) = v;
        }
        if (r_hi < NNODES) {
            float2 v = make_float2(c[nt].z + b0, c[nt].w + b1);
            *(float2*)(C + (size_t)r_hi * NCOLS + col) = v;
        }
    }
}

// ---------------- launch ----------------------------------------------------------
extern "C" void kernel_launch(void* const* d_in, const int* in_sizes, int n_in,
                              void* d_out, int out_size) {
    const float* x     = (const float*)d_in[0];
    const int*   ei    = (const int*)d_in[1];
    const float* W_in  = (const float*)d_in[2];
    const float* b_in  = (const float*)d_in[3];
    const float* W1    = (const float*)d_in[4];
    const float* b1    = (const float*)d_in[5];
    const float* W2    = (const float*)d_in[6];
    const float* b2    = (const float*)d_in[7];
    const float* W3    = (const float*)d_in[8];
    const float* b3    = (const float*)d_in[9];
    const float* W_out = (const float*)d_in[10];
    const float* b_out = (const float*)d_in[11];
    float* out = (float*)d_out;

    const int* src = ei;            // edge_index[0]
    const int* dst = ei + NEDGES;   // edge_index[1]

    const int gemm_grid = (NNODES + 127) / 128;
    const int agg_grid  = (NNODES + 7) / 8;

    // CSR build; layer-0 GEMM only needs g_dis (from scan1), interleave it.
    k_zero<<<(NNODES + 255) / 256, 256>>>();
    k_count<<<(NEDGES + 255) / 256, 256>>>(dst);
    k_scan1<<<NB_SCAN, SCAN_B>>>();
    k_scan2<<<1, 128>>>();
    k_gemm_tf32<F_IN, 0><<<gemm_grid, 256>>>(x, 0, W_in);
    k_scan3<<<NB_SCAN, SCAN_B>>>();
    k_fill<<<(NEDGES + 255) / 256, 256>>>(src, dst);
    k_agg<<<agg_grid, 256>>>(b_in, 0 * HID);

    const float* Ws[3] = {W1, W2, W3};
    const float* bs[3] = {b1, b2, b3};
    for (int l = 1; l < NL; l++) {
        k_gemm_tf32<HID, 1><<<gemm_grid, 256>>>(nullptr, (l - 1) * HID, Ws[l - 1]);
        k_agg<<<agg_grid, 256>>>(bs[l - 1], l * HID);
    }

    k_gemm_out_tf32<<<gemm_grid, 256>>>(W_out, b_out, out);
}

// round 6
// speedup vs baseline: 2.9689x; 1.2934x over previous
#include <cuda_runtime.h>
#include <cuda_fp16.h>
#include <cstdint>

#define NNODES 100000
#define NEDGES 1600000
#define F_IN   256
#define HID    128
#define NL     4
#define NCOLS  40
#define JKDIM  (HID * NL)   // 512

// ---------------- device scratch (allocation-free rule: __device__ globals) --------
__device__ __align__(16) __half g_t[(size_t)NNODES * HID];   // u = dis*(A@W) (25.6 MB)
__device__ __align__(16) __half g_h[(size_t)NNODES * JKDIM]; // JK concat, fp16 (102.4 MB)
__device__ __align__(16) __half g_wt[102400];                // transposed fp16 weights
__device__ int   g_cnt[NNODES];
__device__ int   g_cur[NNODES];
__device__ int   g_off[NNODES + 1];
__device__ float g_dis[NNODES];
__device__ int   g_col[NEDGES];
__device__ int   g_bsum[128];

// transposed-weight offsets inside g_wt ([n][k] layouts)
#define WT_IN   0            // [128][256]
#define WT_1    32768        // [128][128]
#define WT_2    49152
#define WT_3    65536
#define WT_OUT  81920        // [40][512]

#define SCAN_B 1024
#define NB_SCAN ((NNODES + SCAN_B - 1) / SCAN_B)     // 98

// ---------------- fp16 MMA helper ---------------------------------------------------
__device__ __forceinline__ void mma_f16(float4& c, const uint32_t a[4],
                                        uint32_t b0, uint32_t b1) {
    asm volatile(
        "mma.sync.aligned.m16n8k16.row.col.f32.f16.f16.f32 "
        "{%0,%1,%2,%3}, {%4,%5,%6,%7}, {%8,%9}, {%0,%1,%2,%3};"
        : "+f"(c.x), "+f"(c.y), "+f"(c.z), "+f"(c.w)
        : "r"(a[0]), "r"(a[1]), "r"(a[2]), "r"(a[3]), "r"(b0), "r"(b1));
}

// ---------------- weight prep: transpose + fp16 convert -----------------------------
__global__ void k_prep_w(const float* __restrict__ W_in, const float* __restrict__ W1,
                         const float* __restrict__ W2, const float* __restrict__ W3,
                         const float* __restrict__ W_out) {
    int i = blockIdx.x * blockDim.x + threadIdx.x;
    if (i < 32768) {                       // W_in [256][128] -> [128][256]
        int k = i >> 7, n = i & 127;
        g_wt[WT_IN + n * F_IN + k] = __float2half(W_in[i]);
    } else if (i < 32768 + 3 * 16384) {    // W1..W3 [128][128] -> [128][128]
        int j = i - 32768;
        int w = j >> 14, r = j & 16383;
        int k = r >> 7, n = r & 127;
        const float* W = (w == 0) ? W1 : (w == 1) ? W2 : W3;
        g_wt[WT_1 + w * 16384 + n * HID + k] = __float2half(W[r]);
    } else if (i < 102400) {               // W_out [512][40] -> [40][512]
        int j = i - 81920;
        int k = j / NCOLS, n = j % NCOLS;
        g_wt[WT_OUT + n * JKDIM + k] = __float2half(W_out[j]);
    }
}

// ---------------- CSR construction ------------------------------------------------
__global__ void k_zero() {
    int i = blockIdx.x * blockDim.x + threadIdx.x;
    if (i < NNODES) { g_cnt[i] = 0; g_cur[i] = 0; }
}

__global__ void k_count(const int* __restrict__ dst) {
    int e = blockIdx.x * blockDim.x + threadIdx.x;
    if (e < NEDGES) atomicAdd(&g_cnt[dst[e]], 1);
}

__global__ void k_scan1() {
    __shared__ int s[SCAN_B];
    int tid = threadIdx.x;
    int idx = blockIdx.x * SCAN_B + tid;
    int v = (idx < NNODES) ? g_cnt[idx] : 0;
    if (idx < NNODES) g_dis[idx] = rsqrtf((float)(v + 1));   // +1 self loop
    s[tid] = v;
    __syncthreads();
    #pragma unroll
    for (int o = 1; o < SCAN_B; o <<= 1) {
        int t = (tid >= o) ? s[tid - o] : 0;
        __syncthreads();
        s[tid] += t;
        __syncthreads();
    }
    if (idx < NNODES) g_off[idx] = s[tid] - v;
    if (tid == SCAN_B - 1) g_bsum[blockIdx.x] = s[tid];
}

__global__ void k_scan2() {
    __shared__ int s[128];
    int tid = threadIdx.x;
    if (tid < NB_SCAN) s[tid] = g_bsum[tid];
    __syncthreads();
    if (tid == 0) {
        int a = 0;
        for (int i = 0; i < NB_SCAN; i++) { int t = s[i]; s[i] = a; a += t; }
    }
    __syncthreads();
    if (tid < NB_SCAN) g_bsum[tid] = s[tid];
}

__global__ void k_scan3() {
    int idx = blockIdx.x * SCAN_B + threadIdx.x;
    if (idx < NNODES) g_off[idx] += g_bsum[blockIdx.x];
    if (idx == 0) g_off[NNODES] = NEDGES;
}

__global__ void k_fill(const int* __restrict__ src, const int* __restrict__ dst) {
    int e = blockIdx.x * blockDim.x + threadIdx.x;
    if (e < NEDGES) {
        int d = dst[e];
        int pos = g_off[d] + atomicAdd(&g_cur[d], 1);
        g_col[pos] = src[e];
    }
}

// ---------------- fp16 GEMM: [N x K] @ Wt -> g_t (fp16, scaled by dis[row]) --------
// BM=128, BN=128(all), BK=32; 8 warps (4 m x 2 n); warp tile 32x64.
// FROM_H=1 reads g_h (fp16, stride JKDIM) at column src_off; else fp32 A (lda=K).
template <int K, int FROM_H>
__global__ void __launch_bounds__(256) k_gemm_h(const float* __restrict__ A,
                                                int src_off, int wt_off) {
    __shared__ uint32_t Ah[128][20];   // half2; cols 0..15 = k2 within BK=32
    __shared__ uint32_t Ws[128][20];   // half2; Wt rows (n), k2

    int tid = threadIdx.x;
    int lane = tid & 31, wid = tid >> 5;
    int warp_m = wid & 3, warp_n = wid >> 2;
    int row0 = blockIdx.x * 128;
    int g = lane >> 2, tg = lane & 3;

    const __half* Wt = g_wt + wt_off;

    float4 c[2][8];
    #pragma unroll
    for (int mt = 0; mt < 2; mt++)
        #pragma unroll
        for (int nt = 0; nt < 8; nt++)
            c[mt][nt] = make_float4(0.f, 0.f, 0.f, 0.f);

    for (int kc = 0; kc < K; kc += 32) {
        // stage A tile (128 rows x 32 halves)
        #pragma unroll
        for (int j = 0; j < 2; j++) {
            int idx = tid + j * 256;
            int r = idx >> 2, q = idx & 3;       // q: group of 8 halves
            int gr = row0 + r;
            if (FROM_H) {
                uint4 v = make_uint4(0, 0, 0, 0);
                if (gr < NNODES)
                    v = *(const uint4*)(g_h + (size_t)gr * JKDIM + src_off + kc + q * 8);
                *(uint4*)&Ah[r][q * 4] = v;
            } else {
                float4 v0 = make_float4(0.f, 0.f, 0.f, 0.f), v1 = v0;
                if (gr < NNODES) {
                    v0 = *(const float4*)(A + (size_t)gr * K + kc + q * 8);
                    v1 = *(const float4*)(A + (size_t)gr * K + kc + q * 8 + 4);
                }
                __half2 h0 = __floats2half2_rn(v0.x, v0.y);
                __half2 h1 = __floats2half2_rn(v0.z, v0.w);
                __half2 h2 = __floats2half2_rn(v1.x, v1.y);
                __half2 h3 = __floats2half2_rn(v1.z, v1.w);
                uint4 u = make_uint4(*(uint32_t*)&h0, *(uint32_t*)&h1,
                                     *(uint32_t*)&h2, *(uint32_t*)&h3);
                *(uint4*)&Ah[r][q * 4] = u;
            }
        }
        // stage Wt tile (128 n-rows x 32 halves)
        #pragma unroll
        for (int j = 0; j < 2; j++) {
            int idx = tid + j * 256;
            int n = idx >> 2, q = idx & 3;
            uint4 v = *(const uint4*)(Wt + (size_t)n * K + kc + q * 8);
            *(uint4*)&Ws[n][q * 4] = v;
        }
        __syncthreads();

        #pragma unroll
        for (int ks2 = 0; ks2 < 16; ks2 += 8) {   // two k16 steps
            uint32_t a[2][4];
            #pragma unroll
            for (int mt = 0; mt < 2; mt++) {
                int r = warp_m * 32 + mt * 16 + g;
                a[mt][0] = Ah[r][ks2 + tg];
                a[mt][1] = Ah[r + 8][ks2 + tg];
                a[mt][2] = Ah[r][ks2 + tg + 4];
                a[mt][3] = Ah[r + 8][ks2 + tg + 4];
            }
            #pragma unroll
            for (int nt = 0; nt < 8; nt++) {
                int n = warp_n * 64 + nt * 8 + g;
                uint32_t b0 = Ws[n][ks2 + tg];
                uint32_t b1 = Ws[n][ks2 + tg + 4];
                #pragma unroll
                for (int mt = 0; mt < 2; mt++)
                    mma_f16(c[mt][nt], a[mt], b0, b1);
            }
        }
        __syncthreads();
    }

    // epilogue: u = dis[row] * acc -> g_t (fp16)
    #pragma unroll
    for (int mt = 0; mt < 2; mt++) {
        int r_lo = row0 + warp_m * 32 + mt * 16 + g;
        int r_hi = r_lo + 8;
        float dlo = (r_lo < NNODES) ? g_dis[r_lo] : 0.f;
        float dhi = (r_hi < NNODES) ? g_dis[r_hi] : 0.f;
        #pragma unroll
        for (int nt = 0; nt < 8; nt++) {
            int col = warp_n * 64 + nt * 8 + 2 * tg;
            if (r_lo < NNODES) {
                __half2 v = __floats2half2_rn(c[mt][nt].x * dlo, c[mt][nt].y * dlo);
                *(__half2*)(g_t + (size_t)r_lo * HID + col) = v;
            }
            if (r_hi < NNODES) {
                __half2 v = __floats2half2_rn(c[mt][nt].z * dhi, c[mt][nt].w * dhi);
                *(__half2*)(g_t + (size_t)r_hi * HID + col) = v;
            }
        }
    }
}

// ---------------- Aggregation: h[:, dst_off:+128] = relu(dis[d]*(u[d]+Σu[s]) + b) --
__global__ void k_agg(const float* __restrict__ bias, int dst_off) {
    int node = blockIdx.x * 8 + (threadIdx.x >> 5);
    if (node >= NNODES) return;
    int lane = threadIdx.x & 31;

    const uint2* t2 = (const uint2*)g_t;   // 32 x 8B slots per 128-feat row

    auto fetch = [&](int row, float4& dstacc) {
        uint2 raw = __ldg(&t2[(size_t)row * 32 + lane]);
        float2 f01 = __half22float2(*(__half2*)&raw.x);
        float2 f23 = __half22float2(*(__half2*)&raw.y);
        dstacc.x += f01.x; dstacc.y += f01.y;
        dstacc.z += f23.x; dstacc.w += f23.y;
    };

    float4 acc = make_float4(0.f, 0.f, 0.f, 0.f);
    fetch(node, acc);                       // self loop (u[node])

    int e   = g_off[node];
    int end = g_off[node + 1];

    for (; e + 3 < end; e += 4) {
        int s0 = __ldg(&g_col[e]);
        int s1 = __ldg(&g_col[e + 1]);
        int s2 = __ldg(&g_col[e + 2]);
        int s3 = __ldg(&g_col[e + 3]);
        uint2 r0 = __ldg(&t2[(size_t)s0 * 32 + lane]);
        uint2 r1 = __ldg(&t2[(size_t)s1 * 32 + lane]);
        uint2 r2 = __ldg(&t2[(size_t)s2 * 32 + lane]);
        uint2 r3 = __ldg(&t2[(size_t)s3 * 32 + lane]);
        float2 a0 = __half22float2(*(__half2*)&r0.x), b0 = __half22float2(*(__half2*)&r0.y);
        float2 a1 = __half22float2(*(__half2*)&r1.x), b1 = __half22float2(*(__half2*)&r1.y);
        float2 a2 = __half22float2(*(__half2*)&r2.x), b2 = __half22float2(*(__half2*)&r2.y);
        float2 a3 = __half22float2(*(__half2*)&r3.x), b3 = __half22float2(*(__half2*)&r3.y);
        acc.x += (a0.x + a1.x) + (a2.x + a3.x);
        acc.y += (a0.y + a1.y) + (a2.y + a3.y);
        acc.z += (b0.x + b1.x) + (b2.x + b3.x);
        acc.w += (b0.y + b1.y) + (b2.y + b3.y);
    }
    for (; e < end; e++) {
        int s0 = __ldg(&g_col[e]);
        fetch(s0, acc);
    }

    float dnode = __ldg(&g_dis[node]);
    float4 bb = __ldg((const float4*)(bias) + lane);
    acc.x = fmaxf(fmaf(dnode, acc.x, bb.x), 0.f);
    acc.y = fmaxf(fmaf(dnode, acc.y, bb.y), 0.f);
    acc.z = fmaxf(fmaf(dnode, acc.z, bb.z), 0.f);
    acc.w = fmaxf(fmaf(dnode, acc.w, bb.w), 0.f);

    // store fp16 into JK buffer
    __half2 o01 = __floats2half2_rn(acc.x, acc.y);
    __half2 o23 = __floats2half2_rn(acc.z, acc.w);
    uint2 packed = make_uint2(*(uint32_t*)&o01, *(uint32_t*)&o23);
    *(uint2*)(g_h + (size_t)node * JKDIM + dst_off + lane * 4) = packed;
}

// ---------------- fp16 output GEMM: g_h[N x 512] @ Wt_out + b -> out (fp32) --------
// BM=128; 8 warps, each one m16 band covering all 40 cols (5 n8 tiles).
__global__ void __launch_bounds__(256) k_gemm_out_h(const float* __restrict__ b,
                                                    float* __restrict__ C) {
    constexpr int K = JKDIM;
    __shared__ uint32_t Ah[128][20];
    __shared__ uint32_t Ws[40][20];

    int tid = threadIdx.x;
    int lane = tid & 31, wid = tid >> 5;
    int row0 = blockIdx.x * 128;
    int g = lane >> 2, tg = lane & 3;
    int m0 = wid * 16;

    const __half* Wt = g_wt + WT_OUT;

    float4 c[5];
    #pragma unroll
    for (int nt = 0; nt < 5; nt++) c[nt] = make_float4(0.f, 0.f, 0.f, 0.f);

    for (int kc = 0; kc < K; kc += 32) {
        // stage A (128 x 32 halves) from g_h fp16
        #pragma unroll
        for (int j = 0; j < 2; j++) {
            int idx = tid + j * 256;
            int r = idx >> 2, q = idx & 3;
            int gr = row0 + r;
            uint4 v = make_uint4(0, 0, 0, 0);
            if (gr < NNODES)
                v = *(const uint4*)(g_h + (size_t)gr * K + kc + q * 8);
            *(uint4*)&Ah[r][q * 4] = v;
        }
        // stage Wt (40 x 32 halves): 160 uint4
        if (tid < 160) {
            int n = tid >> 2, q = tid & 3;
            uint4 v = *(const uint4*)(Wt + (size_t)n * K + kc + q * 8);
            *(uint4*)&Ws[n][q * 4] = v;
        }
        __syncthreads();

        #pragma unroll
        for (int ks2 = 0; ks2 < 16; ks2 += 8) {
            uint32_t a[4];
            int r = m0 + g;
            a[0] = Ah[r][ks2 + tg];
            a[1] = Ah[r + 8][ks2 + tg];
            a[2] = Ah[r][ks2 + tg + 4];
            a[3] = Ah[r + 8][ks2 + tg + 4];
            #pragma unroll
            for (int nt = 0; nt < 5; nt++) {
                int n = nt * 8 + g;
                uint32_t b0 = Ws[n][ks2 + tg];
                uint32_t b1 = Ws[n][ks2 + tg + 4];
                mma_f16(c[nt], a, b0, b1);
            }
        }
        __syncthreads();
    }

    int r_lo = row0 + m0 + g;
    int r_hi = r_lo + 8;
    #pragma unroll
    for (int nt = 0; nt < 5; nt++) {
        int col = nt * 8 + 2 * tg;
        float b0 = __ldg(&b[col]), b1 = __ldg(&b[col + 1]);
        if (r_lo < NNODES) {
            float2 v = make_float2(c[nt].x + b0, c[nt].y + b1);
            *(float2*)(C + (size_t)r_lo * NCOLS + col) = v;
        }
        if (r_hi < NNODES) {
            float2 v = make_float2(c[nt].z + b0, c[nt].w + b1);
            *(float2*)(C + (size_t)r_hi * NCOLS + col) = v;
        }
    }
}

// ---------------- launch ----------------------------------------------------------
extern "C" void kernel_launch(void* const* d_in, const int* in_sizes, int n_in,
                              void* d_out, int out_size) {
    const float* x     = (const float*)d_in[0];
    const int*   ei    = (const int*)d_in[1];
    const float* W_in  = (const float*)d_in[2];
    const float* b_in  = (const float*)d_in[3];
    const float* W1    = (const float*)d_in[4];
    const float* b1    = (const float*)d_in[5];
    const float* W2    = (const float*)d_in[6];
    const float* b2    = (const float*)d_in[7];
    const float* W3    = (const float*)d_in[8];
    const float* b3    = (const float*)d_in[9];
    const float* W_out = (const float*)d_in[10];
    const float* b_out = (const float*)d_in[11];
    float* out = (float*)d_out;

    const int* src = ei;            // edge_index[0]
    const int* dst = ei + NEDGES;   // edge_index[1]

    const int gemm_grid = (NNODES + 127) / 128;
    const int agg_grid  = (NNODES + 7) / 8;

    // CSR build; layer-0 GEMM only needs g_dis (from scan1), interleave it.
    k_zero<<<(NNODES + 255) / 256, 256>>>();
    k_count<<<(NEDGES + 255) / 256, 256>>>(dst);
    k_prep_w<<<(102400 + 255) / 256, 256>>>(W_in, W1, W2, W3, W_out);
    k_scan1<<<NB_SCAN, SCAN_B>>>();
    k_scan2<<<1, 128>>>();
    k_gemm_h<F_IN, 0><<<gemm_grid, 256>>>(x, 0, WT_IN);
    k_scan3<<<NB_SCAN, SCAN_B>>>();
    k_fill<<<(NEDGES + 255) / 256, 256>>>(src, dst);
    k_agg<<<agg_grid, 256>>>(b_in, 0 * HID);

    const int wt_offs[3] = {WT_1, WT_2, WT_3};
    const float* bs[3] = {b1, b2, b3};
    for (int l = 1; l < NL; l++) {
        k_gemm_h<HID, 1><<<gemm_grid, 256>>>(nullptr, (l - 1) * HID, wt_offs[l - 1]);
        k_agg<<<agg_grid, 256>>>(bs[l - 1], l * HID);
    }

    k_gemm_out_h<<<gemm_grid, 256>>>(b_out, out);
}

// round 8
// speedup vs baseline: 3.1154x; 1.0493x over previous
#include <cuda_runtime.h>
#include <cuda_fp16.h>
#include <cstdint>

#define NNODES 100000
#define NEDGES 1600000
#define F_IN   256
#define HID    128
#define NL     4
#define NCOLS  40
#define JKDIM  (HID * NL)   // 512

// ---------------- device scratch (allocation-free rule: __device__ globals) --------
__device__ __align__(16) __half g_t[(size_t)NNODES * HID];   // u = dis*(A@W) (25.6 MB)
__device__ __align__(16) __half g_h[(size_t)NNODES * JKDIM]; // JK concat, fp16 (102.4 MB)
__device__ __align__(16) __half g_wt[102400];                // transposed fp16 weights
__device__ int   g_cnt[NNODES];
__device__ int   g_cur[NNODES];
__device__ int   g_off[NNODES + 1];
__device__ float g_dis[NNODES];
__device__ int   g_col[NEDGES];
__device__ int   g_bsum[128];

// transposed-weight offsets inside g_wt ([n][k] layouts)
#define WT_IN   0            // [128][256]
#define WT_1    32768        // [128][128]
#define WT_2    49152
#define WT_3    65536
#define WT_OUT  81920        // [40][512]

#define SCAN_B 1024
#define NB_SCAN ((NNODES + SCAN_B - 1) / SCAN_B)     // 98

// smem row stride in uint32 (half2) units: 32 data + 4 pad; 36 % 32 == 4 so
// fragment loads hit banks 4g + tg + const -> all 32 banks, conflict-free.
#define AST 36

// ---------------- fp16 MMA helper ---------------------------------------------------
__device__ __forceinline__ void mma_f16(float4& c, const uint32_t a[4],
                                        uint32_t b0, uint32_t b1) {
    asm volatile(
        "mma.sync.aligned.m16n8k16.row.col.f32.f16.f16.f32 "
        "{%0,%1,%2,%3}, {%4,%5,%6,%7}, {%8,%9}, {%0,%1,%2,%3};"
        : "+f"(c.x), "+f"(c.y), "+f"(c.z), "+f"(c.w)
        : "r"(a[0]), "r"(a[1]), "r"(a[2]), "r"(a[3]), "r"(b0), "r"(b1));
}

// ---------------- weight prep (transpose + fp16) + counter zeroing ------------------
__global__ void k_prep_w(const float* __restrict__ W_in, const float* __restrict__ W1,
                         const float* __restrict__ W2, const float* __restrict__ W3,
                         const float* __restrict__ W_out) {
    int i = blockIdx.x * blockDim.x + threadIdx.x;
    if (i < NNODES) { g_cnt[i] = 0; g_cur[i] = 0; }
    if (i < 32768) {                       // W_in [256][128] -> [128][256]
        int k = i >> 7, n = i & 127;
        g_wt[WT_IN + n * F_IN + k] = __float2half(W_in[i]);
    } else if (i < 32768 + 3 * 16384) {    // W1..W3 [128][128] -> [128][128]
        int j = i - 32768;
        int w = j >> 14, r = j & 16383;
        int k = r >> 7, n = r & 127;
        const float* W = (w == 0) ? W1 : (w == 1) ? W2 : W3;
        g_wt[WT_1 + w * 16384 + n * HID + k] = __float2half(W[r]);
    } else if (i < 102400) {               // W_out [512][40] -> [40][512]
        int j = i - 81920;
        int k = j / NCOLS, n = j % NCOLS;
        g_wt[WT_OUT + n * JKDIM + k] = __float2half(W_out[j]);
    }
}

// ---------------- CSR construction ------------------------------------------------
__global__ void k_count(const int* __restrict__ dst) {
    int e = blockIdx.x * blockDim.x + threadIdx.x;
    if (e < NEDGES) atomicAdd(&g_cnt[dst[e]], 1);
}

__global__ void k_scan1() {
    __shared__ int s[SCAN_B];
    int tid = threadIdx.x;
    int idx = blockIdx.x * SCAN_B + tid;
    int v = (idx < NNODES) ? g_cnt[idx] : 0;
    if (idx < NNODES) g_dis[idx] = rsqrtf((float)(v + 1));   // +1 self loop
    s[tid] = v;
    __syncthreads();
    #pragma unroll
    for (int o = 1; o < SCAN_B; o <<= 1) {
        int t = (tid >= o) ? s[tid - o] : 0;
        __syncthreads();
        s[tid] += t;
        __syncthreads();
    }
    if (idx < NNODES) g_off[idx] = s[tid] - v;
    if (tid == SCAN_B - 1) g_bsum[blockIdx.x] = s[tid];
}

__global__ void k_scan2() {
    __shared__ int s[128];
    int tid = threadIdx.x;
    if (tid < NB_SCAN) s[tid] = g_bsum[tid];
    __syncthreads();
    if (tid == 0) {
        int a = 0;
        for (int i = 0; i < NB_SCAN; i++) { int t = s[i]; s[i] = a; a += t; }
    }
    __syncthreads();
    if (tid < NB_SCAN) g_bsum[tid] = s[tid];
}

__global__ void k_scan3() {
    int idx = blockIdx.x * SCAN_B + threadIdx.x;
    if (idx < NNODES) g_off[idx] += g_bsum[blockIdx.x];
    if (idx == 0) g_off[NNODES] = NEDGES;
}

__global__ void k_fill(const int* __restrict__ src, const int* __restrict__ dst) {
    int e = blockIdx.x * blockDim.x + threadIdx.x;
    if (e < NEDGES) {
        int d = dst[e];
        int pos = g_off[d] + atomicAdd(&g_cur[d], 1);
        g_col[pos] = src[e];
    }
}

// ---------------- fp16 GEMM: [N x K] @ Wt -> g_t (fp16, scaled by dis[row]) --------
// BM=128, full BN=128; BK=64 (static smem, 4 k16 steps between syncs).
// 8 warps (4 m x 2 n); warp tile 32x64.
template <int K, int FROM_H>
__global__ void __launch_bounds__(256) k_gemm_h(const float* __restrict__ A,
                                                int src_off, int wt_off) {
    __shared__ uint32_t Ah[128][AST];   // 128 rows x 32 half2 (+4 pad)
    __shared__ uint32_t Ws[128][AST];   // 128 n-rows x 32 half2

    int tid = threadIdx.x;
    int lane = tid & 31, wid = tid >> 5;
    int warp_m = wid & 3, warp_n = wid >> 2;
    int row0 = blockIdx.x * 128;
    int g = lane >> 2, tg = lane & 3;

    const __half* Wt = g_wt + wt_off;

    float4 c[2][8];
    #pragma unroll
    for (int mt = 0; mt < 2; mt++)
        #pragma unroll
        for (int nt = 0; nt < 8; nt++)
            c[mt][nt] = make_float4(0.f, 0.f, 0.f, 0.f);

    for (int kc = 0; kc < K; kc += 64) {
        // stage A chunk (128 rows x 64 halves): 1024 uint4, 4 per thread
        #pragma unroll
        for (int j = 0; j < 4; j++) {
            int idx = tid + j * 256;
            int r = idx >> 3, q = idx & 7;
            int gr = row0 + r;
            if (FROM_H) {
                uint4 v = make_uint4(0, 0, 0, 0);
                if (gr < NNODES)
                    v = *(const uint4*)(g_h + (size_t)gr * JKDIM + src_off + kc + q * 8);
                *(uint4*)&Ah[r][q * 4] = v;
            } else {
                float4 v0 = make_float4(0.f, 0.f, 0.f, 0.f), v1 = v0;
                if (gr < NNODES) {
                    v0 = *(const float4*)(A + (size_t)gr * K + kc + q * 8);
                    v1 = *(const float4*)(A + (size_t)gr * K + kc + q * 8 + 4);
                }
                __half2 h0 = __floats2half2_rn(v0.x, v0.y);
                __half2 h1 = __floats2half2_rn(v0.z, v0.w);
                __half2 h2 = __floats2half2_rn(v1.x, v1.y);
                __half2 h3 = __floats2half2_rn(v1.z, v1.w);
                uint4 u = make_uint4(*(uint32_t*)&h0, *(uint32_t*)&h1,
                                     *(uint32_t*)&h2, *(uint32_t*)&h3);
                *(uint4*)&Ah[r][q * 4] = u;
            }
        }
        // stage Wt chunk (128 n-rows x 64 halves)
        #pragma unroll
        for (int j = 0; j < 4; j++) {
            int idx = tid + j * 256;
            int n = idx >> 3, q = idx & 7;
            uint4 v = *(const uint4*)(Wt + (size_t)n * K + kc + q * 8);
            *(uint4*)&Ws[n][q * 4] = v;
        }
        __syncthreads();

        #pragma unroll
        for (int s = 0; s < 4; s++) {            // 4 k16 steps per chunk
            int k2 = s * 8;
            uint32_t a[2][4];
            #pragma unroll
            for (int mt = 0; mt < 2; mt++) {
                int r = warp_m * 32 + mt * 16 + g;
                a[mt][0] = Ah[r][k2 + tg];
                a[mt][1] = Ah[r + 8][k2 + tg];
                a[mt][2] = Ah[r][k2 + tg + 4];
                a[mt][3] = Ah[r + 8][k2 + tg + 4];
            }
            #pragma unroll
            for (int nt = 0; nt < 8; nt++) {
                int n = warp_n * 64 + nt * 8 + g;
                uint32_t b0 = Ws[n][k2 + tg];
                uint32_t b1 = Ws[n][k2 + tg + 4];
                #pragma unroll
                for (int mt = 0; mt < 2; mt++)
                    mma_f16(c[mt][nt], a[mt], b0, b1);
            }
        }
        if (kc + 64 < K) __syncthreads();
    }

    // epilogue: u = dis[row] * acc -> g_t (fp16)
    #pragma unroll
    for (int mt = 0; mt < 2; mt++) {
        int r_lo = row0 + warp_m * 32 + mt * 16 + g;
        int r_hi = r_lo + 8;
        float dlo = (r_lo < NNODES) ? g_dis[r_lo] : 0.f;
        float dhi = (r_hi < NNODES) ? g_dis[r_hi] : 0.f;
        #pragma unroll
        for (int nt = 0; nt < 8; nt++) {
            int col = warp_n * 64 + nt * 8 + 2 * tg;
            if (r_lo < NNODES) {
                __half2 v = __floats2half2_rn(c[mt][nt].x * dlo, c[mt][nt].y * dlo);
                *(__half2*)(g_t + (size_t)r_lo * HID + col) = v;
            }
            if (r_hi < NNODES) {
                __half2 v = __floats2half2_rn(c[mt][nt].z * dhi, c[mt][nt].w * dhi);
                *(__half2*)(g_t + (size_t)r_hi * HID + col) = v;
            }
        }
    }
}

// ---------------- Aggregation: h[:, dst_off:+128] = relu(dis[d]*(u[d]+Σu[s]) + b) --
// One warp per node; lane handles 4 halves (8 B). Gather loop unrolled 8-deep.
__global__ void k_agg(const float* __restrict__ bias, int dst_off) {
    int node = blockIdx.x * 8 + (threadIdx.x >> 5);
    if (node >= NNODES) return;
    int lane = threadIdx.x & 31;

    const uint2* t2 = (const uint2*)g_t;

    auto addin = [&](uint2 raw, float4& a) {
        float2 f01 = __half22float2(*(__half2*)&raw.x);
        float2 f23 = __half22float2(*(__half2*)&raw.y);
        a.x += f01.x; a.y += f01.y; a.z += f23.x; a.w += f23.y;
    };

    float4 acc = make_float4(0.f, 0.f, 0.f, 0.f);
    addin(__ldg(&t2[(size_t)node * 32 + lane]), acc);       // self loop

    int e   = g_off[node];
    int end = g_off[node + 1];

    for (; e + 7 < end; e += 8) {
        int s[8];
        #pragma unroll
        for (int i = 0; i < 8; i++) s[i] = __ldg(&g_col[e + i]);
        uint2 r[8];
        #pragma unroll
        for (int i = 0; i < 8; i++) r[i] = __ldg(&t2[(size_t)s[i] * 32 + lane]);
        #pragma unroll
        for (int i = 0; i < 8; i++) addin(r[i], acc);
    }
    for (; e + 1 < end; e += 2) {
        int s0 = __ldg(&g_col[e]);
        int s1 = __ldg(&g_col[e + 1]);
        uint2 r0 = __ldg(&t2[(size_t)s0 * 32 + lane]);
        uint2 r1 = __ldg(&t2[(size_t)s1 * 32 + lane]);
        addin(r0, acc); addin(r1, acc);
    }
    if (e < end) {
        int s0 = __ldg(&g_col[e]);
        addin(__ldg(&t2[(size_t)s0 * 32 + lane]), acc);
    }

    float dnode = __ldg(&g_dis[node]);
    float4 bb = __ldg((const float4*)(bias) + lane);
    acc.x = fmaxf(fmaf(dnode, acc.x, bb.x), 0.f);
    acc.y = fmaxf(fmaf(dnode, acc.y, bb.y), 0.f);
    acc.z = fmaxf(fmaf(dnode, acc.z, bb.z), 0.f);
    acc.w = fmaxf(fmaf(dnode, acc.w, bb.w), 0.f);

    __half2 o01 = __floats2half2_rn(acc.x, acc.y);
    __half2 o23 = __floats2half2_rn(acc.z, acc.w);
    uint2 packed = make_uint2(*(uint32_t*)&o01, *(uint32_t*)&o23);
    *(uint2*)(g_h + (size_t)node * JKDIM + dst_off + lane * 4) = packed;
}

// ---------------- fp16 output GEMM: g_h[N x 512] @ Wt_out + b -> out (fp32) --------
// BM=128, BK=64; A and W_out chunks staged per iteration (static smem, 24 KB).
__global__ void __launch_bounds__(256) k_gemm_out_h(const float* __restrict__ b,
                                                    float* __restrict__ C) {
    constexpr int K = JKDIM;
    __shared__ uint32_t Ah[128][AST];
    __shared__ uint32_t Ws[40][AST];

    int tid = threadIdx.x;
    int lane = tid & 31, wid = tid >> 5;
    int row0 = blockIdx.x * 128;
    int g = lane >> 2, tg = lane & 3;
    int m0 = wid * 16;

    const __half* Wt = g_wt + WT_OUT;

    float4 c[5];
    #pragma unroll
    for (int nt = 0; nt < 5; nt++) c[nt] = make_float4(0.f, 0.f, 0.f, 0.f);

    #pragma unroll
    for (int chunk = 0; chunk < 8; chunk++) {
        int kc = chunk * 64;
        // stage A chunk (128 x 64 halves): 1024 uint4, 4 per thread
        #pragma unroll
        for (int j = 0; j < 4; j++) {
            int idx = tid + j * 256;
            int r = idx >> 3, q = idx & 7;
            int gr = row0 + r;
            uint4 v = make_uint4(0, 0, 0, 0);
            if (gr < NNODES)
                v = *(const uint4*)(g_h + (size_t)gr * K + kc + q * 8);
            *(uint4*)&Ah[r][q * 4] = v;
        }
        // stage W_out chunk (40 x 64 halves): 320 uint4
        for (int idx = tid; idx < 320; idx += 256) {
            int n = idx >> 3, q = idx & 7;
            uint4 v = *(const uint4*)(Wt + (size_t)n * K + kc + q * 8);
            *(uint4*)&Ws[n][q * 4] = v;
        }
        __syncthreads();

        #pragma unroll
        for (int s = 0; s < 4; s++) {
            int k2 = s * 8;
            uint32_t a[4];
            int r = m0 + g;
            a[0] = Ah[r][k2 + tg];
            a[1] = Ah[r + 8][k2 + tg];
            a[2] = Ah[r][k2 + tg + 4];
            a[3] = Ah[r + 8][k2 + tg + 4];
            #pragma unroll
            for (int nt = 0; nt < 5; nt++) {
                int n = nt * 8 + g;
                uint32_t b0 = Ws[n][k2 + tg];
                uint32_t b1 = Ws[n][k2 + tg + 4];
                mma_f16(c[nt], a, b0, b1);
            }
        }
        __syncthreads();
    }

    int r_lo = row0 + m0 + g;
    int r_hi = r_lo + 8;
    #pragma unroll
    for (int nt = 0; nt < 5; nt++) {
        int col = nt * 8 + 2 * tg;
        float b0 = __ldg(&b[col]), b1 = __ldg(&b[col + 1]);
        if (r_lo < NNODES) {
            float2 v = make_float2(c[nt].x + b0, c[nt].y + b1);
            *(float2*)(C + (size_t)r_lo * NCOLS + col) = v;
        }
        if (r_hi < NNODES) {
            float2 v = make_float2(c[nt].z + b0, c[nt].w + b1);
            *(float2*)(C + (size_t)r_hi * NCOLS + col) = v;
        }
    }
}

// ---------------- launch ----------------------------------------------------------
extern "C" void kernel_launch(void* const* d_in, const int* in_sizes, int n_in,
                              void* d_out, int out_size) {
    const float* x     = (const float*)d_in[0];
    const int*   ei    = (const int*)d_in[1];
    const float* W_in  = (const float*)d_in[2];
    const float* b_in  = (const float*)d_in[3];
    const float* W1    = (const float*)d_in[4];
    const float* b1    = (const float*)d_in[5];
    const float* W2    = (const float*)d_in[6];
    const float* b2    = (const float*)d_in[7];
    const float* W3    = (const float*)d_in[8];
    const float* b3    = (const float*)d_in[9];
    const float* W_out = (const float*)d_in[10];
    const float* b_out = (const float*)d_in[11];
    float* out = (float*)d_out;

    const int* src = ei;            // edge_index[0]
    const int* dst = ei + NEDGES;   // edge_index[1]

    const int gemm_grid = (NNODES + 127) / 128;
    const int agg_grid  = (NNODES + 7) / 8;

    k_prep_w<<<(102400 + 255) / 256, 256>>>(W_in, W1, W2, W3, W_out);  // also zeros cnt/cur
    k_count<<<(NEDGES + 255) / 256, 256>>>(dst);
    k_scan1<<<NB_SCAN, SCAN_B>>>();
    k_scan2<<<1, 128>>>();
    k_gemm_h<F_IN, 0><<<gemm_grid, 256>>>(x, 0, WT_IN);
    k_scan3<<<NB_SCAN, SCAN_B>>>();
    k_fill<<<(NEDGES + 255) / 256, 256>>>(src, dst);
    k_agg<<<agg_grid, 256>>>(b_in, 0 * HID);

    const int wt_offs[3] = {WT_1, WT_2, WT_3};
    const float* bs[3] = {b1, b2, b3};
    for (int l = 1; l < NL; l++) {
        k_gemm_h<HID, 1><<<gemm_grid, 256>>>(nullptr, (l - 1) * HID, wt_offs[l - 1]);
        k_agg<<<agg_grid, 256>>>(bs[l - 1], l * HID);
    }

    k_gemm_out_h<<<gemm_grid, 256>>>(b_out, out);
}